// round 6
// baseline (speedup 1.0000x reference)
#include <cuda_runtime.h>
#include <cuda_fp16.h>
#include <cstdint>

// ---------------------------------------------------------------------------
// LiquidNeuralNetwork via mma.sync HMMA.
// 2-product GEMMs: Ah*Wh + Ah*Wl (A fp16-hi, W fp16 hi/lo split), fp32 accum.
// CTA = 256 rows, 16 warps x 16 rows, warps fully decoupled in the main loop.
// y, accY, D, AH in registers (<=128); DOPRI5 stage accumulators as fp16
// half2 in SMEM updated with HFMA2; k1 passed to stage 1 via D registers.
// ---------------------------------------------------------------------------

#define LNN_DIN    14
#define LNN_DOUT   3
#define LNN_M      256
#define LNN_NT     512
#define LNN_NSTEPS 32

// SMEM byte offsets
#define OFF_W1   0            // [4kt][8j][32lane] uint4 {h01,h89,l01,l89} = 16KB
#define OFF_W2   16384
#define OFF_ACC  32768        // 4 arrays [m][16w][4p][32lane] uint4 = 128KB
#define OFF_WIN  163840       // 14*64 f32
#define OFF_BIN  167424
#define OFF_B1   167680
#define OFF_B2   167936
#define OFF_WOUT 168192       // 64*3 f32
#define OFF_BOUT 168960
#define SMEM_SZ  168976

// DOPRI5 tableau
#define C_A21 (float)(1.0/5.0)
static __device__ constexpr float CT[5][5] = {
    {0.f, (float)(3.0/40.0), (float)(44.0/45.0), (float)(19372.0/6561.0), (float)(9017.0/3168.0)},
    {0.f, (float)(9.0/40.0), (float)(-56.0/15.0), (float)(-25360.0/2187.0), (float)(-355.0/33.0)},
    {0.f, 0.f, (float)(32.0/9.0), (float)(64448.0/6561.0), (float)(46732.0/5247.0)},
    {0.f, 0.f, 0.f, (float)(-212.0/729.0), (float)(49.0/176.0)},
    {0.f, 0.f, 0.f, 0.f, (float)(-5103.0/18656.0)},
};
static __device__ constexpr float BC[6] = {
    (float)(35.0/384.0), 0.f, (float)(500.0/1113.0), (float)(125.0/192.0),
    (float)(-2187.0/6784.0), (float)(11.0/84.0)};

__device__ __forceinline__ void mma8(float* d, uint32_t a0, uint32_t a1,
                                     uint32_t a2, uint32_t a3,
                                     uint32_t b0, uint32_t b1) {
    asm("mma.sync.aligned.m16n8k16.row.col.f32.f16.f16.f32 "
        "{%0,%1,%2,%3}, {%4,%5,%6,%7}, {%8,%9}, {%0,%1,%2,%3};"
        : "+f"(d[0]), "+f"(d[1]), "+f"(d[2]), "+f"(d[3])
        : "r"(a0), "r"(a1), "r"(a2), "r"(a3), "r"(b0), "r"(b1));
}

__device__ __forceinline__ uint32_t packh2(float a, float b) {
    __half2 h = __floats2half2_rn(a, b);
    return *reinterpret_cast<uint32_t*>(&h);
}
__device__ __forceinline__ uint32_t hfma2u(uint32_t a, uint32_t b, uint32_t c) {
    __half2 r = __hfma2(*reinterpret_cast<__half2*>(&a),
                        *reinterpret_cast<__half2*>(&b),
                        *reinterpret_cast<__half2*>(&c));
    return *reinterpret_cast<uint32_t*>(&r);
}
__device__ __forceinline__ uint32_t hmul2u(uint32_t a, uint32_t b) {
    __half2 r = __hmul2(*reinterpret_cast<__half2*>(&a),
                        *reinterpret_cast<__half2*>(&b));
    return *reinterpret_cast<uint32_t*>(&r);
}
__device__ __forceinline__ void pack_hilo(float a, float b,
                                          uint32_t& h, uint32_t& l) {
    __half2 H = __floats2half2_rn(a, b);
    float2 f = __half22float2(H);
    __half2 L = __floats2half2_rn(a - f.x, b - f.y);
    h = *reinterpret_cast<uint32_t*>(&H);
    l = *reinterpret_cast<uint32_t*>(&L);
}
__device__ __forceinline__ float fast_tanh(float x) {
    float ax = fabsf(x);
    float e  = __expf(-2.0f * ax);
    float t  = __fdividef(1.0f - e, 1.0f + e);
    return copysignf(t, x);
}

// D = A(hi) @ (Wh + Wl): 2 MMAs per fragment, K=64, N=64.
__device__ __forceinline__ void gemm2p(float* D, const uint32_t* AH,
                                       const char* Wf, int lane) {
#pragma unroll
    for (int i = 0; i < 32; ++i) D[i] = 0.0f;
#pragma unroll
    for (int j = 0; j < 8; ++j) {
#pragma unroll
        for (int kt = 0; kt < 4; ++kt) {
            uint4 f = *reinterpret_cast<const uint4*>(
                Wf + (((kt * 8 + j) * 32) + lane) * 16);
            mma8(D + 4 * j, AH[4*kt], AH[4*kt+1], AH[4*kt+2], AH[4*kt+3], f.x, f.y);
            mma8(D + 4 * j, AH[4*kt], AH[4*kt+1], AH[4*kt+2], AH[4*kt+3], f.z, f.w);
        }
    }
}

__global__ __launch_bounds__(LNN_NT)
void lnn2276_v6_kernel(const float* __restrict__ x,
                       const float* __restrict__ ts,
                       const float* __restrict__ gWin, const float* __restrict__ gbin,
                       const float* __restrict__ gW1,  const float* __restrict__ gb1,
                       const float* __restrict__ gW2,  const float* __restrict__ gb2,
                       const float* __restrict__ gWout, const float* __restrict__ gbout,
                       float* __restrict__ out, int B) {
    extern __shared__ char sm[];
    const int tid  = threadIdx.x;
    const int w    = tid >> 5;
    const int lane = tid & 31;
    const int g    = lane >> 2;
    const int tig  = lane & 3;

    // ---- prologue: W fragments (hi/lo interleaved uint4) ----
    for (int p = tid; p < 1024; p += LNN_NT) {
        int kt = p >> 8, j = (p >> 5) & 7, ln = p & 31;
        int tg = ln & 3, gg = ln >> 2;
        int k0 = kt * 16 + 2 * tg;
        int n  = 8 * j + gg;
        float a0 = gW1[k0 * 64 + n],       a1 = gW1[(k0 + 1) * 64 + n];
        float a2 = gW1[(k0 + 8) * 64 + n], a3 = gW1[(k0 + 9) * 64 + n];
        uint32_t h0, l0, h1, l1;
        pack_hilo(a0, a1, h0, l0);
        pack_hilo(a2, a3, h1, l1);
        *reinterpret_cast<uint4*>(sm + OFF_W1 + p * 16) = make_uint4(h0, h1, l0, l1);
        a0 = gW2[k0 * 64 + n];       a1 = gW2[(k0 + 1) * 64 + n];
        a2 = gW2[(k0 + 8) * 64 + n]; a3 = gW2[(k0 + 9) * 64 + n];
        pack_hilo(a0, a1, h0, l0);
        pack_hilo(a2, a3, h1, l1);
        *reinterpret_cast<uint4*>(sm + OFF_W2 + p * 16) = make_uint4(h0, h1, l0, l1);
    }
    for (int i = tid; i < LNN_DIN * 64; i += LNN_NT)
        *(float*)(sm + OFF_WIN + i * 4) = gWin[i];
    for (int i = tid; i < 64 * LNN_DOUT; i += LNN_NT)
        *(float*)(sm + OFF_WOUT + i * 4) = gWout[i];
    if (tid < 64) {
        *(float*)(sm + OFF_BIN + tid * 4) = gbin[tid];
        *(float*)(sm + OFF_B1 + tid * 4)  = gb1[tid];
        *(float*)(sm + OFF_B2 + tid * 4)  = gb2[tid];
    }
    if (tid < LNN_DOUT) *(float*)(sm + OFF_BOUT + tid * 4) = gbout[tid];
    __syncthreads();

    const float dt = (ts[1] - ts[0]) * (1.0f / (float)LNN_NSTEPS);
    const uint32_t dt2  = packh2(dt, dt);
    const uint32_t cA21 = packh2(dt * C_A21, dt * C_A21);
    const int r1 = blockIdx.x * LNN_M + w * 16 + g;
    const int r2 = r1 + 8;

    // ---- y0 = x @ Win + bin in D-fragment layout ----
    float y[32];
    {
        float xr1[LNN_DIN], xr2[LNN_DIN];
#pragma unroll
        for (int k = 0; k < LNN_DIN; ++k) {
            xr1[k] = (r1 < B) ? x[(size_t)r1 * LNN_DIN + k] : 0.0f;
            xr2[k] = (r2 < B) ? x[(size_t)r2 * LNN_DIN + k] : 0.0f;
        }
#pragma unroll
        for (int j = 0; j < 8; ++j) {
            int c0 = 8 * j + 2 * tig;
            float s0 = *(const float*)(sm + OFF_BIN + c0 * 4);
            float s1 = *(const float*)(sm + OFF_BIN + (c0 + 1) * 4);
            float a0 = s0, a1 = s1, a2 = s0, a3 = s1;
#pragma unroll
            for (int k = 0; k < LNN_DIN; ++k) {
                float w0 = *(const float*)(sm + OFF_WIN + (k * 64 + c0) * 4);
                float w1 = *(const float*)(sm + OFF_WIN + (k * 64 + c0 + 1) * 4);
                a0 = fmaf(xr1[k], w0, a0);
                a1 = fmaf(xr1[k], w1, a1);
                a2 = fmaf(xr2[k], w0, a2);
                a3 = fmaf(xr2[k], w1, a3);
            }
            y[4*j+0] = a0; y[4*j+1] = a1; y[4*j+2] = a2; y[4*j+3] = a3;
        }
    }

    // thread-private ACC slice: + m*32768 + p*512
    char* accT = sm + OFF_ACC + (w * 128 + lane) * 16;

    float accY[32], D[32];
    uint32_t AH[16];

#pragma unroll 1
    for (int step = 0; step < LNN_NSTEPS; ++step) {
#pragma unroll
        for (int s = 0; s < 6; ++s) {
            // ---- u-build -> AH (fp16 hi of u) ----
#pragma unroll
            for (int p = 0; p < 4; ++p) {
                uint32_t yh[4];
#pragma unroll
                for (int q = 0; q < 4; ++q)
                    yh[q] = packh2(y[8*p + 2*q], y[8*p + 2*q + 1]);
                if (s == 0) {
#pragma unroll
                    for (int q = 0; q < 4; ++q) AH[4*p + q] = yh[q];
                } else if (s == 1) {
#pragma unroll
                    for (int q = 0; q < 4; ++q) {
                        uint32_t kh = packh2(D[8*p + 2*q], D[8*p + 2*q + 1]);
                        AH[4*p + q] = hfma2u(cA21, kh, yh[q]);
                    }
                } else {
                    uint4 a = *reinterpret_cast<const uint4*>(
                        accT + (s - 2) * 32768 + p * 512);
                    AH[4*p + 0] = hfma2u(dt2, a.x, yh[0]);
                    AH[4*p + 1] = hfma2u(dt2, a.y, yh[1]);
                    AH[4*p + 2] = hfma2u(dt2, a.z, yh[2]);
                    AH[4*p + 3] = hfma2u(dt2, a.w, yh[3]);
                }
            }
            // ---- GEMM1, tanh ----
            gemm2p(D, AH, sm + OFF_W1, lane);
#pragma unroll
            for (int j = 0; j < 8; ++j) {
                float2 bb = *(const float2*)(sm + OFF_B1 + (8*j + 2*tig) * 4);
                float t0 = fast_tanh(D[4*j+0] + bb.x);
                float t1 = fast_tanh(D[4*j+1] + bb.y);
                float t2 = fast_tanh(D[4*j+2] + bb.x);
                float t3 = fast_tanh(D[4*j+3] + bb.y);
                int t4 = 4 * (j >> 1) + 2 * (j & 1);
                AH[t4]     = packh2(t0, t1);
                AH[t4 + 1] = packh2(t2, t3);
            }
            // ---- GEMM2 + bias -> k (in D) ----
            gemm2p(D, AH, sm + OFF_W2, lane);
#pragma unroll
            for (int j = 0; j < 8; ++j) {
                float2 bb = *(const float2*)(sm + OFF_B2 + (8*j + 2*tig) * 4);
                D[4*j+0] += bb.x; D[4*j+1] += bb.y;
                D[4*j+2] += bb.x; D[4*j+3] += bb.y;
            }
            // ---- accY ----
            if (s == 0) {
#pragma unroll
                for (int i = 0; i < 32; ++i) accY[i] = BC[0] * D[i];
            } else if (s != 1) {
#pragma unroll
                for (int i = 0; i < 32; ++i) accY[i] = fmaf(BC[s], D[i], accY[i]);
            }
            // ---- stage-combination arrays (fp16 HFMA2 RMW) ----
            if (s < 5) {
                uint32_t kh[16];
#pragma unroll
                for (int p = 0; p < 4; ++p)
#pragma unroll
                    for (int q = 0; q < 4; ++q)
                        kh[4*p + q] = packh2(D[8*p + 2*q], D[8*p + 2*q + 1]);
#pragma unroll
                for (int m = 1; m < 5; ++m) {
                    if (m >= s) {
                        float cf = CT[s][m];
                        uint32_t c2 = packh2(cf, cf);
                        char* ab = accT + (m - 1) * 32768;
#pragma unroll
                        for (int p = 0; p < 4; ++p) {
                            uint4 a;
                            if (s == 0) {
                                a.x = hmul2u(c2, kh[4*p+0]);
                                a.y = hmul2u(c2, kh[4*p+1]);
                                a.z = hmul2u(c2, kh[4*p+2]);
                                a.w = hmul2u(c2, kh[4*p+3]);
                            } else {
                                a = *reinterpret_cast<const uint4*>(ab + p * 512);
                                a.x = hfma2u(c2, kh[4*p+0], a.x);
                                a.y = hfma2u(c2, kh[4*p+1], a.y);
                                a.z = hfma2u(c2, kh[4*p+2], a.z);
                                a.w = hfma2u(c2, kh[4*p+3], a.w);
                            }
                            *reinterpret_cast<uint4*>(ab + p * 512) = a;
                        }
                    }
                }
            }
        }
        // ---- y += dt * accY ----
#pragma unroll
        for (int i = 0; i < 32; ++i) y[i] = fmaf(dt, accY[i], y[i]);
    }

    // ---- out = y @ Wout + bout (quad shfl reduction) ----
    {
        float o1[LNN_DOUT] = {0.f, 0.f, 0.f};
        float o2[LNN_DOUT] = {0.f, 0.f, 0.f};
#pragma unroll
        for (int j = 0; j < 8; ++j) {
#pragma unroll
            for (int e = 0; e < 2; ++e) {
                int col = 8 * j + 2 * tig + e;
#pragma unroll
                for (int q = 0; q < LNN_DOUT; ++q) {
                    float wv = *(const float*)(sm + OFF_WOUT + (col * LNN_DOUT + q) * 4);
                    o1[q] = fmaf(y[4*j+e],   wv, o1[q]);
                    o2[q] = fmaf(y[4*j+2+e], wv, o2[q]);
                }
            }
        }
#pragma unroll
        for (int q = 0; q < LNN_DOUT; ++q) {
            o1[q] += __shfl_xor_sync(0xffffffffu, o1[q], 1);
            o1[q] += __shfl_xor_sync(0xffffffffu, o1[q], 2);
            o2[q] += __shfl_xor_sync(0xffffffffu, o2[q], 1);
            o2[q] += __shfl_xor_sync(0xffffffffu, o2[q], 2);
        }
        if (tig == 0) {
#pragma unroll
            for (int q = 0; q < LNN_DOUT; ++q) {
                float bo = *(const float*)(sm + OFF_BOUT + q * 4);
                if (r1 < B) out[(size_t)r1 * LNN_DOUT + q] = o1[q] + bo;
                if (r2 < B) out[(size_t)r2 * LNN_DOUT + q] = o2[q] + bo;
            }
        }
    }
}

extern "C" void kernel_launch(void* const* d_in, const int* in_sizes, int n_in,
                              void* d_out, int out_size) {
    const float* x    = (const float*)d_in[0];
    const float* ts   = (const float*)d_in[1];
    const float* Win  = (const float*)d_in[2];
    const float* bin  = (const float*)d_in[3];
    const float* W1   = (const float*)d_in[4];
    const float* b1   = (const float*)d_in[5];
    const float* W2   = (const float*)d_in[6];
    const float* b2   = (const float*)d_in[7];
    const float* Wout = (const float*)d_in[8];
    const float* bout = (const float*)d_in[9];
    float* out = (float*)d_out;

    int B = in_sizes[0] / LNN_DIN;
    cudaFuncSetAttribute(lnn2276_v6_kernel,
                         cudaFuncAttributeMaxDynamicSharedMemorySize, SMEM_SZ);
    int grid = (B + LNN_M - 1) / LNN_M;
    lnn2276_v6_kernel<<<grid, LNN_NT, SMEM_SZ>>>(x, ts, Win, bin, W1, b1, W2, b2,
                                                 Wout, bout, out, B);
}

// round 7
// speedup vs baseline: 2.4764x; 2.4764x over previous
#include <cuda_runtime.h>
#include <cuda_fp16.h>
#include <cstdint>

// ---------------------------------------------------------------------------
// LiquidNeuralNetwork via mma.sync HMMA.
// 2-product GEMMs: Ah*Wh + Ah*Wl (A fp16-hi, W fp16 hi/lo split), fp32 accum.
// CTA = 64 rows, 4 warps x 16 rows, warps fully decoupled in the main loop.
// launch_bounds(128,3): 3 CTAs/SM, no spills. y, accY, D, AH in registers;
// DOPRI5 stage accumulators as fp16 half2 in SMEM (HFMA2 RMW); k1 passed to
// stage 1 through the still-live D registers.
// ---------------------------------------------------------------------------

#define LNN_DIN    14
#define LNN_DOUT   3
#define LNN_M      64
#define LNN_NT     128
#define LNN_NSTEPS 32

// SMEM byte offsets
#define OFF_W1   0            // [4kt][8j][32lane] uint4 {h01,h89,l01,l89} = 16KB
#define OFF_W2   16384
#define OFF_ACC  32768        // 4 arrays x [4w][4p][32lane] uint4 = 32KB
#define OFF_WIN  65536        // 14*64 f32
#define OFF_BIN  69120
#define OFF_B1   69376
#define OFF_B2   69632
#define OFF_WOUT 69888        // 64*3 f32
#define OFF_BOUT 70656
#define SMEM_SZ  70672

// DOPRI5 tableau
#define C_A21 (float)(1.0/5.0)
static __device__ constexpr float CT[5][5] = {
    {0.f, (float)(3.0/40.0), (float)(44.0/45.0), (float)(19372.0/6561.0), (float)(9017.0/3168.0)},
    {0.f, (float)(9.0/40.0), (float)(-56.0/15.0), (float)(-25360.0/2187.0), (float)(-355.0/33.0)},
    {0.f, 0.f, (float)(32.0/9.0), (float)(64448.0/6561.0), (float)(46732.0/5247.0)},
    {0.f, 0.f, 0.f, (float)(-212.0/729.0), (float)(49.0/176.0)},
    {0.f, 0.f, 0.f, 0.f, (float)(-5103.0/18656.0)},
};
static __device__ constexpr float BC[6] = {
    (float)(35.0/384.0), 0.f, (float)(500.0/1113.0), (float)(125.0/192.0),
    (float)(-2187.0/6784.0), (float)(11.0/84.0)};

__device__ __forceinline__ void mma8(float* d, uint32_t a0, uint32_t a1,
                                     uint32_t a2, uint32_t a3,
                                     uint32_t b0, uint32_t b1) {
    asm("mma.sync.aligned.m16n8k16.row.col.f32.f16.f16.f32 "
        "{%0,%1,%2,%3}, {%4,%5,%6,%7}, {%8,%9}, {%0,%1,%2,%3};"
        : "+f"(d[0]), "+f"(d[1]), "+f"(d[2]), "+f"(d[3])
        : "r"(a0), "r"(a1), "r"(a2), "r"(a3), "r"(b0), "r"(b1));
}

__device__ __forceinline__ uint32_t packh2(float a, float b) {
    __half2 h = __floats2half2_rn(a, b);
    return *reinterpret_cast<uint32_t*>(&h);
}
__device__ __forceinline__ uint32_t hfma2u(uint32_t a, uint32_t b, uint32_t c) {
    __half2 r = __hfma2(*reinterpret_cast<__half2*>(&a),
                        *reinterpret_cast<__half2*>(&b),
                        *reinterpret_cast<__half2*>(&c));
    return *reinterpret_cast<uint32_t*>(&r);
}
__device__ __forceinline__ uint32_t hmul2u(uint32_t a, uint32_t b) {
    __half2 r = __hmul2(*reinterpret_cast<__half2*>(&a),
                        *reinterpret_cast<__half2*>(&b));
    return *reinterpret_cast<uint32_t*>(&r);
}
__device__ __forceinline__ void pack_hilo(float a, float b,
                                          uint32_t& h, uint32_t& l) {
    __half2 H = __floats2half2_rn(a, b);
    float2 f = __half22float2(H);
    __half2 L = __floats2half2_rn(a - f.x, b - f.y);
    h = *reinterpret_cast<uint32_t*>(&H);
    l = *reinterpret_cast<uint32_t*>(&L);
}
__device__ __forceinline__ float fast_tanh(float x) {
    float ax = fabsf(x);
    float e  = __expf(-2.0f * ax);
    float t  = __fdividef(1.0f - e, 1.0f + e);
    return copysignf(t, x);
}

// D = A(hi) @ (Wh + Wl): 2 MMAs per fragment, K=64, N=64.
__device__ __forceinline__ void gemm2p(float* D, const uint32_t* AH,
                                       const char* Wf, int lane) {
#pragma unroll
    for (int i = 0; i < 32; ++i) D[i] = 0.0f;
#pragma unroll
    for (int j = 0; j < 8; ++j) {
#pragma unroll
        for (int kt = 0; kt < 4; ++kt) {
            uint4 f = *reinterpret_cast<const uint4*>(
                Wf + (((kt * 8 + j) * 32) + lane) * 16);
            mma8(D + 4 * j, AH[4*kt], AH[4*kt+1], AH[4*kt+2], AH[4*kt+3], f.x, f.y);
            mma8(D + 4 * j, AH[4*kt], AH[4*kt+1], AH[4*kt+2], AH[4*kt+3], f.z, f.w);
        }
    }
}

__global__ __launch_bounds__(LNN_NT, 3)
void lnn2276_v7_kernel(const float* __restrict__ x,
                       const float* __restrict__ ts,
                       const float* __restrict__ gWin, const float* __restrict__ gbin,
                       const float* __restrict__ gW1,  const float* __restrict__ gb1,
                       const float* __restrict__ gW2,  const float* __restrict__ gb2,
                       const float* __restrict__ gWout, const float* __restrict__ gbout,
                       float* __restrict__ out, int B) {
    extern __shared__ char sm[];
    const int tid  = threadIdx.x;
    const int w    = tid >> 5;
    const int lane = tid & 31;
    const int g    = lane >> 2;
    const int tig  = lane & 3;

    // ---- prologue: W fragments (hi/lo interleaved uint4) ----
    for (int p = tid; p < 1024; p += LNN_NT) {
        int kt = p >> 8, j = (p >> 5) & 7, ln = p & 31;
        int tg = ln & 3, gg = ln >> 2;
        int k0 = kt * 16 + 2 * tg;
        int n  = 8 * j + gg;
        float a0 = gW1[k0 * 64 + n],       a1 = gW1[(k0 + 1) * 64 + n];
        float a2 = gW1[(k0 + 8) * 64 + n], a3 = gW1[(k0 + 9) * 64 + n];
        uint32_t h0, l0, h1, l1;
        pack_hilo(a0, a1, h0, l0);
        pack_hilo(a2, a3, h1, l1);
        *reinterpret_cast<uint4*>(sm + OFF_W1 + p * 16) = make_uint4(h0, h1, l0, l1);
        a0 = gW2[k0 * 64 + n];       a1 = gW2[(k0 + 1) * 64 + n];
        a2 = gW2[(k0 + 8) * 64 + n]; a3 = gW2[(k0 + 9) * 64 + n];
        pack_hilo(a0, a1, h0, l0);
        pack_hilo(a2, a3, h1, l1);
        *reinterpret_cast<uint4*>(sm + OFF_W2 + p * 16) = make_uint4(h0, h1, l0, l1);
    }
    for (int i = tid; i < LNN_DIN * 64; i += LNN_NT)
        *(float*)(sm + OFF_WIN + i * 4) = gWin[i];
    for (int i = tid; i < 64 * LNN_DOUT; i += LNN_NT)
        *(float*)(sm + OFF_WOUT + i * 4) = gWout[i];
    if (tid < 64) {
        *(float*)(sm + OFF_BIN + tid * 4) = gbin[tid];
        *(float*)(sm + OFF_B1 + tid * 4)  = gb1[tid];
        *(float*)(sm + OFF_B2 + tid * 4)  = gb2[tid];
    }
    if (tid < LNN_DOUT) *(float*)(sm + OFF_BOUT + tid * 4) = gbout[tid];
    __syncthreads();

    const float dt = (ts[1] - ts[0]) * (1.0f / (float)LNN_NSTEPS);
    const uint32_t dt2  = packh2(dt, dt);
    const uint32_t cA21 = packh2(dt * C_A21, dt * C_A21);
    const int r1 = blockIdx.x * LNN_M + w * 16 + g;
    const int r2 = r1 + 8;

    // ---- y0 = x @ Win + bin in D-fragment layout ----
    float y[32];
    {
        float xr1[LNN_DIN], xr2[LNN_DIN];
#pragma unroll
        for (int k = 0; k < LNN_DIN; ++k) {
            xr1[k] = (r1 < B) ? x[(size_t)r1 * LNN_DIN + k] : 0.0f;
            xr2[k] = (r2 < B) ? x[(size_t)r2 * LNN_DIN + k] : 0.0f;
        }
#pragma unroll
        for (int j = 0; j < 8; ++j) {
            int c0 = 8 * j + 2 * tig;
            float s0 = *(const float*)(sm + OFF_BIN + c0 * 4);
            float s1 = *(const float*)(sm + OFF_BIN + (c0 + 1) * 4);
            float a0 = s0, a1 = s1, a2 = s0, a3 = s1;
#pragma unroll
            for (int k = 0; k < LNN_DIN; ++k) {
                float w0 = *(const float*)(sm + OFF_WIN + (k * 64 + c0) * 4);
                float w1 = *(const float*)(sm + OFF_WIN + (k * 64 + c0 + 1) * 4);
                a0 = fmaf(xr1[k], w0, a0);
                a1 = fmaf(xr1[k], w1, a1);
                a2 = fmaf(xr2[k], w0, a2);
                a3 = fmaf(xr2[k], w1, a3);
            }
            y[4*j+0] = a0; y[4*j+1] = a1; y[4*j+2] = a2; y[4*j+3] = a3;
        }
    }

    // thread-private ACC slice: + m*8192 + p*512
    char* accT = sm + OFF_ACC + (w * 128 + lane) * 16;

    float accY[32], D[32];
    uint32_t AH[16];

#pragma unroll 1
    for (int step = 0; step < LNN_NSTEPS; ++step) {
#pragma unroll
        for (int s = 0; s < 6; ++s) {
            // ---- u-build -> AH (fp16 hi of u) ----
#pragma unroll
            for (int p = 0; p < 4; ++p) {
                uint32_t yh[4];
#pragma unroll
                for (int q = 0; q < 4; ++q)
                    yh[q] = packh2(y[8*p + 2*q], y[8*p + 2*q + 1]);
                if (s == 0) {
#pragma unroll
                    for (int q = 0; q < 4; ++q) AH[4*p + q] = yh[q];
                } else if (s == 1) {
#pragma unroll
                    for (int q = 0; q < 4; ++q) {
                        uint32_t kh = packh2(D[8*p + 2*q], D[8*p + 2*q + 1]);
                        AH[4*p + q] = hfma2u(cA21, kh, yh[q]);
                    }
                } else {
                    uint4 a = *reinterpret_cast<const uint4*>(
                        accT + (s - 2) * 8192 + p * 512);
                    AH[4*p + 0] = hfma2u(dt2, a.x, yh[0]);
                    AH[4*p + 1] = hfma2u(dt2, a.y, yh[1]);
                    AH[4*p + 2] = hfma2u(dt2, a.z, yh[2]);
                    AH[4*p + 3] = hfma2u(dt2, a.w, yh[3]);
                }
            }
            // ---- GEMM1, tanh ----
            gemm2p(D, AH, sm + OFF_W1, lane);
#pragma unroll
            for (int j = 0; j < 8; ++j) {
                float2 bb = *(const float2*)(sm + OFF_B1 + (8*j + 2*tig) * 4);
                float t0 = fast_tanh(D[4*j+0] + bb.x);
                float t1 = fast_tanh(D[4*j+1] + bb.y);
                float t2 = fast_tanh(D[4*j+2] + bb.x);
                float t3 = fast_tanh(D[4*j+3] + bb.y);
                int t4 = 4 * (j >> 1) + 2 * (j & 1);
                AH[t4]     = packh2(t0, t1);
                AH[t4 + 1] = packh2(t2, t3);
            }
            // ---- GEMM2 + bias -> k (in D) ----
            gemm2p(D, AH, sm + OFF_W2, lane);
#pragma unroll
            for (int j = 0; j < 8; ++j) {
                float2 bb = *(const float2*)(sm + OFF_B2 + (8*j + 2*tig) * 4);
                D[4*j+0] += bb.x; D[4*j+1] += bb.y;
                D[4*j+2] += bb.x; D[4*j+3] += bb.y;
            }
            // ---- accY ----
            if (s == 0) {
#pragma unroll
                for (int i = 0; i < 32; ++i) accY[i] = BC[0] * D[i];
            } else if (s != 1) {
#pragma unroll
                for (int i = 0; i < 32; ++i) accY[i] = fmaf(BC[s], D[i], accY[i]);
            }
            // ---- stage-combination arrays (fp16 HFMA2 RMW) ----
            if (s < 5) {
                uint32_t kh[16];
#pragma unroll
                for (int p = 0; p < 4; ++p)
#pragma unroll
                    for (int q = 0; q < 4; ++q)
                        kh[4*p + q] = packh2(D[8*p + 2*q], D[8*p + 2*q + 1]);
#pragma unroll
                for (int m = 1; m < 5; ++m) {
                    if (m >= s) {
                        float cf = CT[s][m];
                        uint32_t c2 = packh2(cf, cf);
                        char* ab = accT + (m - 1) * 8192;
#pragma unroll
                        for (int p = 0; p < 4; ++p) {
                            uint4 a;
                            if (s == 0) {
                                a.x = hmul2u(c2, kh[4*p+0]);
                                a.y = hmul2u(c2, kh[4*p+1]);
                                a.z = hmul2u(c2, kh[4*p+2]);
                                a.w = hmul2u(c2, kh[4*p+3]);
                            } else {
                                a = *reinterpret_cast<const uint4*>(ab + p * 512);
                                a.x = hfma2u(c2, kh[4*p+0], a.x);
                                a.y = hfma2u(c2, kh[4*p+1], a.y);
                                a.z = hfma2u(c2, kh[4*p+2], a.z);
                                a.w = hfma2u(c2, kh[4*p+3], a.w);
                            }
                            *reinterpret_cast<uint4*>(ab + p * 512) = a;
                        }
                    }
                }
            }
        }
        // ---- y += dt * accY ----
#pragma unroll
        for (int i = 0; i < 32; ++i) y[i] = fmaf(dt, accY[i], y[i]);
    }

    // ---- out = y @ Wout + bout (quad shfl reduction) ----
    {
        float o1[LNN_DOUT] = {0.f, 0.f, 0.f};
        float o2[LNN_DOUT] = {0.f, 0.f, 0.f};
#pragma unroll
        for (int j = 0; j < 8; ++j) {
#pragma unroll
            for (int e = 0; e < 2; ++e) {
                int col = 8 * j + 2 * tig + e;
#pragma unroll
                for (int q = 0; q < LNN_DOUT; ++q) {
                    float wv = *(const float*)(sm + OFF_WOUT + (col * LNN_DOUT + q) * 4);
                    o1[q] = fmaf(y[4*j+e],   wv, o1[q]);
                    o2[q] = fmaf(y[4*j+2+e], wv, o2[q]);
                }
            }
        }
#pragma unroll
        for (int q = 0; q < LNN_DOUT; ++q) {
            o1[q] += __shfl_xor_sync(0xffffffffu, o1[q], 1);
            o1[q] += __shfl_xor_sync(0xffffffffu, o1[q], 2);
            o2[q] += __shfl_xor_sync(0xffffffffu, o2[q], 1);
            o2[q] += __shfl_xor_sync(0xffffffffu, o2[q], 2);
        }
        if (tig == 0) {
#pragma unroll
            for (int q = 0; q < LNN_DOUT; ++q) {
                float bo = *(const float*)(sm + OFF_BOUT + q * 4);
                if (r1 < B) out[(size_t)r1 * LNN_DOUT + q] = o1[q] + bo;
                if (r2 < B) out[(size_t)r2 * LNN_DOUT + q] = o2[q] + bo;
            }
        }
    }
}

extern "C" void kernel_launch(void* const* d_in, const int* in_sizes, int n_in,
                              void* d_out, int out_size) {
    const float* x    = (const float*)d_in[0];
    const float* ts   = (const float*)d_in[1];
    const float* Win  = (const float*)d_in[2];
    const float* bin  = (const float*)d_in[3];
    const float* W1   = (const float*)d_in[4];
    const float* b1   = (const float*)d_in[5];
    const float* W2   = (const float*)d_in[6];
    const float* b2   = (const float*)d_in[7];
    const float* Wout = (const float*)d_in[8];
    const float* bout = (const float*)d_in[9];
    float* out = (float*)d_out;

    int B = in_sizes[0] / LNN_DIN;
    cudaFuncSetAttribute(lnn2276_v7_kernel,
                         cudaFuncAttributeMaxDynamicSharedMemorySize, SMEM_SZ);
    int grid = (B + LNN_M - 1) / LNN_M;
    lnn2276_v7_kernel<<<grid, LNN_NT, SMEM_SZ>>>(x, ts, Win, bin, W1, b1, W2, b2,
                                                 Wout, bout, out, B);
}

// round 8
// speedup vs baseline: 9.8324x; 3.9704x over previous
#include <cuda_runtime.h>
#include <cuda_fp16.h>
#include <cstdint>

// ---------------------------------------------------------------------------
// LiquidNeuralNetwork via mma.sync HMMA.
// 2-product GEMMs: Ah*Wh + Ah*Wl (A fp16-hi, W fp16 hi/lo split), fp32 accum.
// CTA = 64 rows, 4 warps x 16 rows, decoupled warps. launch_bounds(128,2):
// reg cap 256 -> no spills; 2 CTAs/SM by SMEM (8 warps/SM).
// Stage loop NOT unrolled (unroll 1) - data-driven DOPRI5 via 5 fp16 SMEM
// accumulator arrays; y, accY, D, AH in registers.
// ---------------------------------------------------------------------------

#define LNN_DIN    14
#define LNN_DOUT   3
#define LNN_M      64
#define LNN_NT     128
#define LNN_NSTEPS 32

// SMEM byte offsets
#define OFF_W1   0            // [4kt][8j][32lane] uint4 {h01,h89,l01,l89} = 16KB
#define OFF_W2   16384
#define OFF_ACC  32768        // 5 arrays x 8192B ([4w][4p][32lane] uint4)
#define OFF_WIN  73728        // 14*64 f32
#define OFF_BIN  77312
#define OFF_B1   77568
#define OFF_B2   77824
#define OFF_WOUT 78080        // 64*3 f32
#define OFF_BOUT 78848
#define SMEM_SZ  78864

// DOPRI5: CT2[s][m] = coefficient of k_{s+1} in the input sum of stage m+2
static __device__ constexpr float CT2[5][5] = {
    {(float)(1.0/5.0), (float)(3.0/40.0), (float)(44.0/45.0),
     (float)(19372.0/6561.0), (float)(9017.0/3168.0)},
    {0.f, (float)(9.0/40.0), (float)(-56.0/15.0),
     (float)(-25360.0/2187.0), (float)(-355.0/33.0)},
    {0.f, 0.f, (float)(32.0/9.0), (float)(64448.0/6561.0), (float)(46732.0/5247.0)},
    {0.f, 0.f, 0.f, (float)(-212.0/729.0), (float)(49.0/176.0)},
    {0.f, 0.f, 0.f, 0.f, (float)(-5103.0/18656.0)},
};
static __device__ constexpr float BC[6] = {
    (float)(35.0/384.0), 0.f, (float)(500.0/1113.0), (float)(125.0/192.0),
    (float)(-2187.0/6784.0), (float)(11.0/84.0)};

__device__ __forceinline__ void mma8(float* d, uint32_t a0, uint32_t a1,
                                     uint32_t a2, uint32_t a3,
                                     uint32_t b0, uint32_t b1) {
    asm("mma.sync.aligned.m16n8k16.row.col.f32.f16.f16.f32 "
        "{%0,%1,%2,%3}, {%4,%5,%6,%7}, {%8,%9}, {%0,%1,%2,%3};"
        : "+f"(d[0]), "+f"(d[1]), "+f"(d[2]), "+f"(d[3])
        : "r"(a0), "r"(a1), "r"(a2), "r"(a3), "r"(b0), "r"(b1));
}

__device__ __forceinline__ uint32_t packh2(float a, float b) {
    __half2 h = __floats2half2_rn(a, b);
    return *reinterpret_cast<uint32_t*>(&h);
}
__device__ __forceinline__ uint32_t hfma2u(uint32_t a, uint32_t b, uint32_t c) {
    __half2 r = __hfma2(*reinterpret_cast<__half2*>(&a),
                        *reinterpret_cast<__half2*>(&b),
                        *reinterpret_cast<__half2*>(&c));
    return *reinterpret_cast<uint32_t*>(&r);
}
__device__ __forceinline__ uint32_t hmul2u(uint32_t a, uint32_t b) {
    __half2 r = __hmul2(*reinterpret_cast<__half2*>(&a),
                        *reinterpret_cast<__half2*>(&b));
    return *reinterpret_cast<uint32_t*>(&r);
}
__device__ __forceinline__ void pack_hilo(float a, float b,
                                          uint32_t& h, uint32_t& l) {
    __half2 H = __floats2half2_rn(a, b);
    float2 f = __half22float2(H);
    __half2 L = __floats2half2_rn(a - f.x, b - f.y);
    h = *reinterpret_cast<uint32_t*>(&H);
    l = *reinterpret_cast<uint32_t*>(&L);
}
__device__ __forceinline__ float fast_tanh(float x) {
    float ax = fabsf(x);
    float e  = __expf(-2.0f * ax);
    float t  = __fdividef(1.0f - e, 1.0f + e);
    return copysignf(t, x);
}

// D = A(hi) @ (Wh + Wl): 2 MMAs per fragment, K=64, N=64.
__device__ __forceinline__ void gemm2p(float* D, const uint32_t* AH,
                                       const char* Wf, int lane) {
#pragma unroll
    for (int i = 0; i < 32; ++i) D[i] = 0.0f;
#pragma unroll
    for (int j = 0; j < 8; ++j) {
#pragma unroll
        for (int kt = 0; kt < 4; ++kt) {
            uint4 f = *reinterpret_cast<const uint4*>(
                Wf + (((kt * 8 + j) * 32) + lane) * 16);
            mma8(D + 4 * j, AH[4*kt], AH[4*kt+1], AH[4*kt+2], AH[4*kt+3], f.x, f.y);
            mma8(D + 4 * j, AH[4*kt], AH[4*kt+1], AH[4*kt+2], AH[4*kt+3], f.z, f.w);
        }
    }
}

__global__ __launch_bounds__(LNN_NT, 2)
void lnn2276_v8_kernel(const float* __restrict__ x,
                       const float* __restrict__ ts,
                       const float* __restrict__ gWin, const float* __restrict__ gbin,
                       const float* __restrict__ gW1,  const float* __restrict__ gb1,
                       const float* __restrict__ gW2,  const float* __restrict__ gb2,
                       const float* __restrict__ gWout, const float* __restrict__ gbout,
                       float* __restrict__ out, int B) {
    extern __shared__ char sm[];
    const int tid  = threadIdx.x;
    const int w    = tid >> 5;
    const int lane = tid & 31;
    const int g    = lane >> 2;
    const int tig  = lane & 3;

    // ---- prologue: W fragments (hi/lo interleaved uint4) ----
    for (int p = tid; p < 1024; p += LNN_NT) {
        int kt = p >> 8, j = (p >> 5) & 7, ln = p & 31;
        int tg = ln & 3, gg = ln >> 2;
        int k0 = kt * 16 + 2 * tg;
        int n  = 8 * j + gg;
        float a0 = gW1[k0 * 64 + n],       a1 = gW1[(k0 + 1) * 64 + n];
        float a2 = gW1[(k0 + 8) * 64 + n], a3 = gW1[(k0 + 9) * 64 + n];
        uint32_t h0, l0, h1, l1;
        pack_hilo(a0, a1, h0, l0);
        pack_hilo(a2, a3, h1, l1);
        *reinterpret_cast<uint4*>(sm + OFF_W1 + p * 16) = make_uint4(h0, h1, l0, l1);
        a0 = gW2[k0 * 64 + n];       a1 = gW2[(k0 + 1) * 64 + n];
        a2 = gW2[(k0 + 8) * 64 + n]; a3 = gW2[(k0 + 9) * 64 + n];
        pack_hilo(a0, a1, h0, l0);
        pack_hilo(a2, a3, h1, l1);
        *reinterpret_cast<uint4*>(sm + OFF_W2 + p * 16) = make_uint4(h0, h1, l0, l1);
    }
    for (int i = tid; i < LNN_DIN * 64; i += LNN_NT)
        *(float*)(sm + OFF_WIN + i * 4) = gWin[i];
    for (int i = tid; i < 64 * LNN_DOUT; i += LNN_NT)
        *(float*)(sm + OFF_WOUT + i * 4) = gWout[i];
    if (tid < 64) {
        *(float*)(sm + OFF_BIN + tid * 4) = gbin[tid];
        *(float*)(sm + OFF_B1 + tid * 4)  = gb1[tid];
        *(float*)(sm + OFF_B2 + tid * 4)  = gb2[tid];
    }
    if (tid < LNN_DOUT) *(float*)(sm + OFF_BOUT + tid * 4) = gbout[tid];
    __syncthreads();

    const float dt = (ts[1] - ts[0]) * (1.0f / (float)LNN_NSTEPS);
    const uint32_t dt2 = packh2(dt, dt);
    const int r1 = blockIdx.x * LNN_M + w * 16 + g;
    const int r2 = r1 + 8;

    // ---- y0 = x @ Win + bin in D-fragment layout ----
    float y[32];
    {
        float xr1[LNN_DIN], xr2[LNN_DIN];
#pragma unroll
        for (int k = 0; k < LNN_DIN; ++k) {
            xr1[k] = (r1 < B) ? x[(size_t)r1 * LNN_DIN + k] : 0.0f;
            xr2[k] = (r2 < B) ? x[(size_t)r2 * LNN_DIN + k] : 0.0f;
        }
#pragma unroll
        for (int j = 0; j < 8; ++j) {
            int c0 = 8 * j + 2 * tig;
            float s0 = *(const float*)(sm + OFF_BIN + c0 * 4);
            float s1 = *(const float*)(sm + OFF_BIN + (c0 + 1) * 4);
            float a0 = s0, a1 = s1, a2 = s0, a3 = s1;
#pragma unroll
            for (int k = 0; k < LNN_DIN; ++k) {
                float w0 = *(const float*)(sm + OFF_WIN + (k * 64 + c0) * 4);
                float w1 = *(const float*)(sm + OFF_WIN + (k * 64 + c0 + 1) * 4);
                a0 = fmaf(xr1[k], w0, a0);
                a1 = fmaf(xr1[k], w1, a1);
                a2 = fmaf(xr2[k], w0, a2);
                a3 = fmaf(xr2[k], w1, a3);
            }
            y[4*j+0] = a0; y[4*j+1] = a1; y[4*j+2] = a2; y[4*j+3] = a3;
        }
    }

    // thread-private ACC slice: + m*8192 + p*512
    char* accT = sm + OFF_ACC + (w * 128 + lane) * 16;

    float accY[32], D[32];
    uint32_t AH[16];

#pragma unroll 1
    for (int step = 0; step < LNN_NSTEPS; ++step) {
#pragma unroll 1
        for (int s = 0; s < 6; ++s) {
            // ---- u-build -> AH (fp16 hi of u) ----
            if (s == 0) {
#pragma unroll
                for (int p = 0; p < 4; ++p)
#pragma unroll
                    for (int q = 0; q < 4; ++q)
                        AH[4*p + q] = packh2(y[8*p + 2*q], y[8*p + 2*q + 1]);
            } else {
                const char* ab = accT + (s - 1) * 8192;
#pragma unroll
                for (int p = 0; p < 4; ++p) {
                    uint4 a = *reinterpret_cast<const uint4*>(ab + p * 512);
                    AH[4*p + 0] = hfma2u(dt2, a.x, packh2(y[8*p+0], y[8*p+1]));
                    AH[4*p + 1] = hfma2u(dt2, a.y, packh2(y[8*p+2], y[8*p+3]));
                    AH[4*p + 2] = hfma2u(dt2, a.z, packh2(y[8*p+4], y[8*p+5]));
                    AH[4*p + 3] = hfma2u(dt2, a.w, packh2(y[8*p+6], y[8*p+7]));
                }
            }
            // ---- GEMM1, tanh ----
            gemm2p(D, AH, sm + OFF_W1, lane);
#pragma unroll
            for (int j = 0; j < 8; ++j) {
                float2 bb = *(const float2*)(sm + OFF_B1 + (8*j + 2*tig) * 4);
                float t0 = fast_tanh(D[4*j+0] + bb.x);
                float t1 = fast_tanh(D[4*j+1] + bb.y);
                float t2 = fast_tanh(D[4*j+2] + bb.x);
                float t3 = fast_tanh(D[4*j+3] + bb.y);
                int t4 = 4 * (j >> 1) + 2 * (j & 1);
                AH[t4]     = packh2(t0, t1);
                AH[t4 + 1] = packh2(t2, t3);
            }
            // ---- GEMM2 + bias -> k (in D) ----
            gemm2p(D, AH, sm + OFF_W2, lane);
#pragma unroll
            for (int j = 0; j < 8; ++j) {
                float2 bb = *(const float2*)(sm + OFF_B2 + (8*j + 2*tig) * 4);
                D[4*j+0] += bb.x; D[4*j+1] += bb.y;
                D[4*j+2] += bb.x; D[4*j+3] += bb.y;
            }
            // ---- accY (BC[1]==0: harmless fma) ----
            float bcs = BC[s];
            if (s == 0) {
#pragma unroll
                for (int i = 0; i < 32; ++i) accY[i] = bcs * D[i];
            } else {
#pragma unroll
                for (int i = 0; i < 32; ++i) accY[i] = fmaf(bcs, D[i], accY[i]);
            }
            // ---- stage-combination arrays (fp16 HFMA2 RMW, predicated) ----
            if (s < 5) {
                uint32_t kh[16];
#pragma unroll
                for (int p = 0; p < 4; ++p)
#pragma unroll
                    for (int q = 0; q < 4; ++q)
                        kh[4*p + q] = packh2(D[8*p + 2*q], D[8*p + 2*q + 1]);
#pragma unroll
                for (int m = 0; m < 5; ++m) {
                    if (m >= s) {
                        float cf = CT2[s][m];
                        uint32_t c2 = packh2(cf, cf);
                        char* ab = accT + m * 8192;
#pragma unroll
                        for (int p = 0; p < 4; ++p) {
                            uint4 a;
                            if (s == 0) {
                                a.x = hmul2u(c2, kh[4*p+0]);
                                a.y = hmul2u(c2, kh[4*p+1]);
                                a.z = hmul2u(c2, kh[4*p+2]);
                                a.w = hmul2u(c2, kh[4*p+3]);
                            } else {
                                a = *reinterpret_cast<const uint4*>(ab + p * 512);
                                a.x = hfma2u(c2, kh[4*p+0], a.x);
                                a.y = hfma2u(c2, kh[4*p+1], a.y);
                                a.z = hfma2u(c2, kh[4*p+2], a.z);
                                a.w = hfma2u(c2, kh[4*p+3], a.w);
                            }
                            *reinterpret_cast<uint4*>(ab + p * 512) = a;
                        }
                    }
                }
            }
        }
        // ---- y += dt * accY ----
#pragma unroll
        for (int i = 0; i < 32; ++i) y[i] = fmaf(dt, accY[i], y[i]);
    }

    // ---- out = y @ Wout + bout (quad shfl reduction) ----
    {
        float o1[LNN_DOUT] = {0.f, 0.f, 0.f};
        float o2[LNN_DOUT] = {0.f, 0.f, 0.f};
#pragma unroll
        for (int j = 0; j < 8; ++j) {
#pragma unroll
            for (int e = 0; e < 2; ++e) {
                int col = 8 * j + 2 * tig + e;
#pragma unroll
                for (int q = 0; q < LNN_DOUT; ++q) {
                    float wv = *(const float*)(sm + OFF_WOUT + (col * LNN_DOUT + q) * 4);
                    o1[q] = fmaf(y[4*j+e],   wv, o1[q]);
                    o2[q] = fmaf(y[4*j+2+e], wv, o2[q]);
                }
            }
        }
#pragma unroll
        for (int q = 0; q < LNN_DOUT; ++q) {
            o1[q] += __shfl_xor_sync(0xffffffffu, o1[q], 1);
            o1[q] += __shfl_xor_sync(0xffffffffu, o1[q], 2);
            o2[q] += __shfl_xor_sync(0xffffffffu, o2[q], 1);
            o2[q] += __shfl_xor_sync(0xffffffffu, o2[q], 2);
        }
        if (tig == 0) {
#pragma unroll
            for (int q = 0; q < LNN_DOUT; ++q) {
                float bo = *(const float*)(sm + OFF_BOUT + q * 4);
                if (r1 < B) out[(size_t)r1 * LNN_DOUT + q] = o1[q] + bo;
                if (r2 < B) out[(size_t)r2 * LNN_DOUT + q] = o2[q] + bo;
            }
        }
    }
}

extern "C" void kernel_launch(void* const* d_in, const int* in_sizes, int n_in,
                              void* d_out, int out_size) {
    const float* x    = (const float*)d_in[0];
    const float* ts   = (const float*)d_in[1];
    const float* Win  = (const float*)d_in[2];
    const float* bin  = (const float*)d_in[3];
    const float* W1   = (const float*)d_in[4];
    const float* b1   = (const float*)d_in[5];
    const float* W2   = (const float*)d_in[6];
    const float* b2   = (const float*)d_in[7];
    const float* Wout = (const float*)d_in[8];
    const float* bout = (const float*)d_in[9];
    float* out = (float*)d_out;

    int B = in_sizes[0] / LNN_DIN;
    cudaFuncSetAttribute(lnn2276_v8_kernel,
                         cudaFuncAttributeMaxDynamicSharedMemorySize, SMEM_SZ);
    int grid = (B + LNN_M - 1) / LNN_M;
    lnn2276_v8_kernel<<<grid, LNN_NT, SMEM_SZ>>>(x, ts, Win, bin, W1, b1, W2, b2,
                                                 Wout, bout, out, B);
}